// round 7
// baseline (speedup 1.0000x reference)
#include <cuda_runtime.h>
#include <cuda_fp16.h>
#include <cstdint>

#define EPS 1e-5f
#define NTH 512
#define CKK 11     // k-slices per warp kept L1-resident via __ldca (2*11*8KB=176KB < ~207KB L1)

// ---------------- device globals (scratch; no allocations allowed) ----------------
// packed recurrent weights: [m][b][r][k=512][rowlocal=256] fp16 ; m=0: whh0, m=1: wih1+whh1
__device__ __half g_warr[2u * 16u * 8u * 512u * 256u];                 // 67.1 MB
__device__ float g_gi0[16u * 256u * 2048u];                            // 33.5 MB: wih0@x + bias0
__device__ float g_bias0[16u * 2048u];
__device__ float g_bias1[16u * 2048u];

// ---------------- PTX helpers ----------------
__device__ __forceinline__ uint32_t smem_u32(const void* p) {
    uint32_t a;
    asm("{ .reg .u64 t; cvta.to.shared.u64 t, %1; cvt.u32.u64 %0, t; }" : "=r"(a) : "l"(p));
    return a;
}
__device__ __forceinline__ uint32_t mapa_u32(uint32_t addr, uint32_t rank) {
    uint32_t r; asm("mapa.shared::cluster.u32 %0, %1, %2;" : "=r"(r) : "r"(addr), "r"(rank));
    return r;
}
__device__ __forceinline__ uint32_t ctarank() {
    uint32_t r; asm("mov.u32 %0, %%cluster_ctarank;" : "=r"(r)); return r;
}
#define CLUSTER_SYNC() do { \
    __syncthreads(); \
    asm volatile("barrier.cluster.arrive.aligned;" ::: "memory"); \
    asm volatile("barrier.cluster.wait.aligned;"   ::: "memory"); \
} while (0)

__device__ __forceinline__ void mb_init(uint32_t mbar, unsigned cnt) {
    asm volatile("mbarrier.init.shared.b64 [%0], %1;" :: "r"(mbar), "r"(cnt) : "memory");
}
// one release-arrive on a (possibly remote) cluster barrier; cumulative release
__device__ __forceinline__ void mb_arrive_rel(uint32_t mbar_cluster_addr) {
    asm volatile("mbarrier.arrive.release.cluster.shared::cluster.b64 _, [%0];"
                 :: "r"(mbar_cluster_addr) : "memory");
}
__device__ __forceinline__ void mb_wait(uint32_t mbar, unsigned parity) {
    unsigned done;
    asm volatile("{\n\t.reg .pred p;\n\t"
        "mbarrier.try_wait.parity.acquire.cluster.shared::cta.b64 p, [%1], %2;\n\t"
        "selp.b32 %0, 1, 0, p;\n\t}"
        : "=r"(done) : "r"(mbar), "r"(parity) : "memory");
    if (!done) {
        asm volatile("{\n\t.reg .pred P1;\n\t"
            "W_%=:\n\t"
            "mbarrier.try_wait.parity.acquire.cluster.shared::cta.b64 P1, [%0], %1, 0x989680;\n\t"
            "@P1 bra.uni D_%=;\n\t"
            "bra.uni W_%=;\n\t"
            "D_%=:\n\t}"
            :: "r"(mbar), "r"(parity) : "memory");
    }
}
__device__ __forceinline__ void st_clu_b32(uint32_t dst, uint32_t val) {
    asm volatile("st.shared::cluster.b32 [%0], %1;" :: "r"(dst), "r"(val) : "memory");
}
__device__ __forceinline__ void st_clu_b64(uint32_t dst, unsigned long long val) {
    asm volatile("st.shared::cluster.b64 [%0], %1;" :: "r"(dst), "l"(val) : "memory");
}
__device__ __forceinline__ float fast_sigmoid(float x) {
    float t;
    asm("ex2.approx.f32 %0, %1;" : "=f"(t) : "f"(-1.4426950408889634f * x));
    float r;
    asm("rcp.approx.f32 %0, %1;" : "=f"(r) : "f"(1.0f + t));
    return r;
}
__device__ __forceinline__ float fast_tanh(float x) {
    float r; asm("tanh.approx.f32 %0, %1;" : "=f"(r) : "f"(x)); return r;
}

// ---------------- K0: bias precompute ----------------
__global__ void k0_init(const float* __restrict__ bih0, const float* __restrict__ bhh0,
                        const float* __restrict__ bih1, const float* __restrict__ bhh1) {
    int i = blockIdx.x * blockDim.x + threadIdx.x;   // 128*256 = 32768 = 16*2048
    g_bias0[i] = bih0[i] + bhh0[i];
    g_bias1[i] = bih1[i] + bhh1[i];
}

// ---------------- K1: pack/transpose recurrent weights to fp16 [k][row] ----------------
__global__ void k1_pack(const float* __restrict__ whh0, const float* __restrict__ wih1,
                        const float* __restrict__ whh1) {
    __shared__ __align__(16) __half sm[64 * 264];
    int kt = blockIdx.x, r = blockIdx.y;
    int mb = blockIdx.z; int m = mb >> 4, b = mb & 15;
    int tid = threadIdx.x;
    int grow = ((tid >> 6) << 9) + (r << 6) + (tid & 63);
    int k0 = kt * 64;
    const float* s0 = (m == 0 ? whh0 : wih1) + ((size_t)(b * 2048 + grow) * 512 + k0);
    const float* s1 = whh1 + ((size_t)(b * 2048 + grow) * 512 + k0);
#pragma unroll
    for (int q = 0; q < 16; q++) {
        float4 v = *(const float4*)(s0 + q * 4);
        if (m) {
            float4 u = *(const float4*)(s1 + q * 4);
            v.x += u.x; v.y += u.y; v.z += u.z; v.w += u.w;
        }
        sm[(q * 4 + 0) * 264 + tid] = __float2half(v.x);
        sm[(q * 4 + 1) * 264 + tid] = __float2half(v.y);
        sm[(q * 4 + 2) * 264 + tid] = __float2half(v.z);
        sm[(q * 4 + 3) * 264 + tid] = __float2half(v.w);
    }
    __syncthreads();
    __half* out = &g_warr[(((size_t)mb) * 8u + r) * 512u * 256u + (size_t)k0 * 256u];
    int kk = tid >> 2, rb = (tid & 3) * 64;
    const uint4* src = (const uint4*)(sm + kk * 264 + rb);
    uint4* dst = (uint4*)(out + kk * 256 + rb);
#pragma unroll
    for (int q = 0; q < 8; q++) dst[q] = src[q];
}

// ---------------- K2: precompute gi0[b][t][row] = wih0@x_t + bias0 ----------------
__global__ void k2_gemm(const float* __restrict__ wih0, const float* __restrict__ x) {
    __shared__ float As[64][17];
    __shared__ float Bs[16][65];
    int rt = blockIdx.x, tt = blockIdx.y, b = blockIdx.z;
    int row0 = rt * 64, t0 = tt * 64;
    int tid = threadIdx.x;
    int lm = tid >> 2, kq = tid & 3;
    const float* Ap = wih0 + ((size_t)(b * 2048 + row0 + lm) * 512 + kq * 4);
    const float* Bp = x + ((size_t)(b * 256 + t0 + lm) * 512 + kq * 4);
    int ty = tid >> 4, tx = tid & 15;
    float C[4][4];
#pragma unroll
    for (int i = 0; i < 4; i++)
#pragma unroll
        for (int j = 0; j < 4; j++) C[i][j] = 0.f;

    for (int kc = 0; kc < 512; kc += 16) {
        float4 a4 = *(const float4*)(Ap + kc);
        float4 b4 = *(const float4*)(Bp + kc);
        As[lm][kq * 4 + 0] = a4.x; As[lm][kq * 4 + 1] = a4.y;
        As[lm][kq * 4 + 2] = a4.z; As[lm][kq * 4 + 3] = a4.w;
        Bs[kq * 4 + 0][lm] = b4.x; Bs[kq * 4 + 1][lm] = b4.y;
        Bs[kq * 4 + 2][lm] = b4.z; Bs[kq * 4 + 3][lm] = b4.w;
        __syncthreads();
#pragma unroll
        for (int kk = 0; kk < 16; kk++) {
            float a[4], bb[4];
#pragma unroll
            for (int i = 0; i < 4; i++) a[i] = As[ty * 4 + i][kk];
#pragma unroll
            for (int j = 0; j < 4; j++) bb[j] = Bs[kk][tx * 4 + j];
#pragma unroll
            for (int i = 0; i < 4; i++)
#pragma unroll
                for (int j = 0; j < 4; j++) C[i][j] += a[i] * bb[j];
        }
        __syncthreads();
    }
    float4 bias = *(const float4*)&g_bias0[b * 2048 + row0 + ty * 4];
#pragma unroll
    for (int j = 0; j < 4; j++) {
        float4 vo;
        vo.x = C[0][j] + bias.x; vo.y = C[1][j] + bias.y;
        vo.z = C[2][j] + bias.z; vo.w = C[3][j] + bias.w;
        *(float4*)&g_gi0[((size_t)(b * 256 + t0 + tx * 4 + j)) * 2048 + row0 + ty * 4] = vo;
    }
}

// ---------------- K3: persistent recurrent kernel ----------------
// 128 CTAs (16 clusters of 8), 512 threads. rank r owns h[64r..64r+64) + its 256 gate rows.
// Warp w (0..15) owns k-range [32w, 32w+32). Exchange: plain DSMEM stores + release-arrive,
// arrive-count barriers (count=8, one per source rank) -> no expect_tx re-arm races.
struct K3Smem {
    float h_s[512];
    float red[16][256];
    float act[256];
    float wpart[16][2];
    float2 stats_in[8][4];   // [src_rank][gate]
    float2 cstat_in[8];      // [src_rank]
    float gw[2][64], gb[2][64];
    float bias1_s[256];
    unsigned long long mb_stats, mb_cstat, mb_h;
};

__global__ void __launch_bounds__(NTH, 1) __cluster_dims__(8, 1, 1)
k3_lstm(const float* __restrict__ ln_w, const float* __restrict__ ln_b, float* __restrict__ y) {
    __shared__ K3Smem S;
    int g = blockIdx.x >> 3;
    uint32_t r = ctarank();
    int tid = threadIdx.x, warp = tid >> 5, lane = tid & 31;
    int gate = tid >> 6, jl = tid & 63;          // valid for tid<256

    uint32_t mbs = smem_u32(&S.mb_stats);
    uint32_t mbc = smem_u32(&S.mb_cstat);
    uint32_t mbh = smem_u32(&S.mb_h);

    // ---- prologue ----
    S.h_s[tid] = 0.f;
    if (tid < 128) {
        int l = tid >> 6, jj = tid & 63;
        S.gw[l][jj] = ln_w[l * 512 + (int)r * 64 + jj];
        S.gb[l][jj] = ln_b[l * 512 + (int)r * 64 + jj];
    }
    if (tid < 256)
        S.bias1_s[tid] = g_bias1[g * 2048 + (gate << 9) + ((int)r << 6) + jl];
    if (tid == 0) { mb_init(mbs, 8); mb_init(mbc, 8); mb_init(mbh, 8); }
    CLUSTER_SYNC();                 // one-time: mbarriers visible cluster-wide

    // cell state: warp 0, lane owns j = 2*lane and 2*lane+1
    float c0 = 0.f, c1 = 0.f;
    unsigned prt = 0;

    const uint4* Wl[2];
    Wl[0] = (const uint4*)&g_warr[(((size_t)(0 * 16 + g)) * 8u + r) * 512u * 256u];
    Wl[1] = (const uint4*)&g_warr[(((size_t)(1 * 16 + g)) * 8u + r) * 512u * 256u];

    for (int t = 0; t < 256; t++) {
        for (int l = 0; l < 2; l++) {
            // ---- prefetch per-row additive term ----
            float gin = 0.f;
            if (tid < 256)
                gin = l ? S.bias1_s[tid]
                        : __ldcg(&g_gi0[((size_t)(g * 256 + t)) * 2048 + (gate << 9) + ((int)r << 6) + jl]);

            // ---- matvec: warp w covers k in [32w,32w+32) over 256 rows ----
            const uint4* Wp = Wl[l] + (size_t)warp * 1024 + lane;
            float acc[8];
#pragma unroll
            for (int i = 0; i < 8; i++) acc[i] = 0.f;
#pragma unroll
            for (int kk = 0; kk < CKK; kk++) {           // L1-resident subset
                uint4 w4 = __ldca(Wp + kk * 32);
                float hk = S.h_s[warp * 32 + kk];
                const __half2* hp = (const __half2*)&w4;
                float2 f0 = __half22float2(hp[0]);
                float2 f1 = __half22float2(hp[1]);
                float2 f2 = __half22float2(hp[2]);
                float2 f3 = __half22float2(hp[3]);
                acc[0] += hk * f0.x; acc[1] += hk * f0.y;
                acc[2] += hk * f1.x; acc[3] += hk * f1.y;
                acc[4] += hk * f2.x; acc[5] += hk * f2.y;
                acc[6] += hk * f3.x; acc[7] += hk * f3.y;
            }
#pragma unroll
            for (int kk = CKK; kk < 32; kk++) {          // streamed from L2
                uint4 w4 = __ldcg(Wp + kk * 32);
                float hk = S.h_s[warp * 32 + kk];
                const __half2* hp = (const __half2*)&w4;
                float2 f0 = __half22float2(hp[0]);
                float2 f1 = __half22float2(hp[1]);
                float2 f2 = __half22float2(hp[2]);
                float2 f3 = __half22float2(hp[3]);
                acc[0] += hk * f0.x; acc[1] += hk * f0.y;
                acc[2] += hk * f1.x; acc[3] += hk * f1.y;
                acc[4] += hk * f2.x; acc[5] += hk * f2.y;
                acc[6] += hk * f3.x; acc[7] += hk * f3.y;
            }
            *(float4*)&S.red[warp][lane * 8]     = make_float4(acc[0], acc[1], acc[2], acc[3]);
            *(float4*)&S.red[warp][lane * 8 + 4] = make_float4(acc[4], acc[5], acc[6], acc[7]);
            __syncthreads();                             // S1: red ready

            float v = gin;
            if (tid < 256) {
#pragma unroll
                for (int w = 0; w < 16; w++) v += S.red[w][tid];
                float s = v, q = v * v;
#pragma unroll
                for (int o = 16; o > 0; o >>= 1) {
                    s += __shfl_xor_sync(0xffffffffu, s, o);
                    q += __shfl_xor_sync(0xffffffffu, q, o);
                }
                if (lane == 0) { S.wpart[warp][0] = s; S.wpart[warp][1] = q; }
            }
            __syncthreads();                             // S2: wpart ready

            // ---- push gate partials to all ranks; single release-arrive per peer ----
            if (warp == 0) {
                if (lane < 4) {
                    float ss = S.wpart[2 * lane][0] + S.wpart[2 * lane + 1][0];
                    float qq = S.wpart[2 * lane][1] + S.wpart[2 * lane + 1][1];
                    unsigned long long pk;
                    asm("mov.b64 %0, {%1, %2};" : "=l"(pk) : "f"(ss), "f"(qq));
                    uint32_t slot = smem_u32(&S.stats_in[r][lane]);
#pragma unroll
                    for (uint32_t rr = 0; rr < 8; rr++)
                        st_clu_b64(mapa_u32(slot, rr), pk);
                }
                __syncwarp();
                if (lane == 0) {
#pragma unroll
                    for (uint32_t rr = 0; rr < 8; rr++)
                        mb_arrive_rel(mapa_u32(mbs, rr));
                }
            }
            mb_wait(mbs, prt);                           // all 8 ranks' gate stats arrived

            if (tid < 256) {
                float Ssum = 0.f, Q = 0.f;
#pragma unroll
                for (int rr = 0; rr < 8; rr++) {
                    float2 p = S.stats_in[rr][gate];
                    Ssum += p.x; Q += p.y;
                }
                float mean = Ssum * (1.f / 512.f);
                float var  = Q * (1.f / 512.f) - mean * mean;
                float rstd = rsqrtf(var + EPS);
                float xn = (v - mean) * rstd * S.gw[l][jl] + S.gb[l][jl];
                S.act[tid] = (gate == 2) ? fast_tanh(xn) : fast_sigmoid(xn);
            }
            __syncthreads();                             // S3: act ready

            float o0 = 0.f, o1 = 0.f;
            if (warp == 0) {
                int j0 = 2 * lane, j1 = 2 * lane + 1;
                float i0 = S.act[j0],       i1 = S.act[j1];
                float f0 = S.act[64 + j0],  f1 = S.act[64 + j1];
                float g0 = S.act[128 + j0], g1 = S.act[128 + j1];
                o0 = S.act[192 + j0];       o1 = S.act[192 + j1];
                c0 = f0 * c0 + i0 * g0;
                c1 = f1 * c1 + i1 * g1;
                float s2 = c0 + c1, q2 = c0 * c0 + c1 * c1;
#pragma unroll
                for (int o = 16; o > 0; o >>= 1) {
                    s2 += __shfl_xor_sync(0xffffffffu, s2, o);
                    q2 += __shfl_xor_sync(0xffffffffu, q2, o);
                }
                if (lane == 0) {
                    unsigned long long pk;
                    asm("mov.b64 %0, {%1, %2};" : "=l"(pk) : "f"(s2), "f"(q2));
                    uint32_t slot = smem_u32(&S.cstat_in[r]);
#pragma unroll
                    for (uint32_t rr = 0; rr < 8; rr++) {
                        st_clu_b64(mapa_u32(slot, rr), pk);
                        mb_arrive_rel(mapa_u32(mbc, rr));
                    }
                }
            }
            mb_wait(mbc, prt);                           // all 8 ranks' c stats arrived

            if (warp == 0) {
                float Sc = 0.f, Qc = 0.f;
#pragma unroll
                for (int rr = 0; rr < 8; rr++) {
                    float2 p = S.cstat_in[rr];
                    Sc += p.x; Qc += p.y;
                }
                float mean = Sc * (1.f / 512.f);
                float var  = Qc * (1.f / 512.f) - mean * mean;
                float rstd = rsqrtf(var + EPS);
                int j0 = 2 * lane, j1 = 2 * lane + 1;
                float h0 = o0 * fast_tanh((c0 - mean) * rstd * S.gw[l][j0] + S.gb[l][j0]);
                float h1 = o1 * fast_tanh((c1 - mean) * rstd * S.gw[l][j1] + S.gb[l][j1]);
                if (l == 1)
                    __stcg((float2*)&y[((size_t)(g * 256 + t)) * 512 + (int)r * 64 + j0],
                           make_float2(h0, h1));
                unsigned long long pk;
                asm("mov.b64 %0, {%1, %2};" : "=l"(pk) : "f"(h0), "f"(h1));
                uint32_t d0 = smem_u32(&S.h_s[(int)r * 64 + j0]);
#pragma unroll
                for (uint32_t rr = 0; rr < 8; rr++)
                    st_clu_b64(mapa_u32(d0, rr), pk);
                __syncwarp();
                if (lane == 0) {
#pragma unroll
                    for (uint32_t rr = 0; rr < 8; rr++)
                        mb_arrive_rel(mapa_u32(mbh, rr));
                }
            }
            mb_wait(mbh, prt);                           // full h vector assembled locally
            prt ^= 1;
        }
    }
    CLUSTER_SYNC();   // drain in-flight remote stores before exit
}

// ---------------- launcher ----------------
extern "C" void kernel_launch(void* const* d_in, const int* in_sizes, int n_in,
                              void* d_out, int out_size) {
    (void)in_sizes; (void)n_in; (void)out_size;
    const float* x    = (const float*)d_in[0];
    const float* wih0 = (const float*)d_in[1];
    const float* whh0 = (const float*)d_in[2];
    const float* bih0 = (const float*)d_in[3];
    const float* bhh0 = (const float*)d_in[4];
    const float* wih1 = (const float*)d_in[5];
    const float* whh1 = (const float*)d_in[6];
    const float* bih1 = (const float*)d_in[7];
    const float* bhh1 = (const float*)d_in[8];
    const float* ln_w = (const float*)d_in[9];
    const float* ln_b = (const float*)d_in[10];
    float* y = (float*)d_out;

    k0_init<<<128, 256>>>(bih0, bhh0, bih1, bhh1);
    k1_pack<<<dim3(8, 8, 32), 256>>>(whh0, wih1, whh1);
    k2_gemm<<<dim3(32, 4, 16), 256>>>(wih0, x);
    k3_lstm<<<128, NTH>>>(ln_w, ln_b, y);
}

// round 9
// speedup vs baseline: 1.7715x; 1.7715x over previous
#include <cuda_runtime.h>
#include <cuda_fp16.h>
#include <cstdint>

#define EPS 1e-5f

// ---------------- device globals (scratch; no allocations allowed) ----------------
// packed recurrent weights: [m][b][r][k=512][rowlocal=256] fp16 ; m=0: whh0, m=1: wih1+whh1
__device__ __half g_warr[2u * 16u * 8u * 512u * 256u];                 // 67.1 MB
__device__ float g_gi0[16u * 256u * 2048u];                            // 33.5 MB: wih0@x + bias0
__device__ float g_bias0[16u * 2048u];
__device__ float g_bias1[16u * 2048u];
__device__ float2 g_part[16u * 8u * 4u];                               // gate stats: [b][rank][gate]
__device__ float2 g_co[16u * 512u];                                    // (c, o) pairs: [b][j]
__device__ unsigned g_cnt[16];
__device__ unsigned g_flag[16];

// ---------------- helpers ----------------
__device__ __forceinline__ float fast_rcp(float x) {
    float r; asm("rcp.approx.f32 %0, %1;" : "=f"(r) : "f"(x)); return r;
}
__device__ __forceinline__ float fast_sigmoid(float x) {
    return fast_rcp(1.0f + __expf(-x));
}
__device__ __forceinline__ float fast_tanh(float x) {
    return 2.0f * fast_rcp(1.0f + __expf(-2.0f * x)) - 1.0f;
}

// group barrier among the 8 CTAs of group g via scoped atomics (no full membar).
__device__ __forceinline__ void group_barrier(int g, unsigned target) {
    __syncthreads();
    if (threadIdx.x == 0) {
        unsigned v;
        asm volatile("atom.add.acq_rel.gpu.global.u32 %0, [%1], 1;"
                     : "=r"(v) : "l"(&g_cnt[g]) : "memory");
        if (v + 1u == target * 8u) {
            asm volatile("st.release.gpu.global.u32 [%0], %1;"
                         :: "l"(&g_flag[g]), "r"(target) : "memory");
        } else {
            unsigned f;
            do {
                asm volatile("ld.acquire.gpu.global.u32 %0, [%1];"
                             : "=r"(f) : "l"(&g_flag[g]) : "memory");
            } while (f < target);
        }
    }
    __syncthreads();
}

// ---------------- K0: per-launch init ----------------
__global__ void k0_init(const float* __restrict__ bih0, const float* __restrict__ bhh0,
                        const float* __restrict__ bih1, const float* __restrict__ bhh1) {
    int i = blockIdx.x * blockDim.x + threadIdx.x;   // 32768 = 16*2048
    g_bias0[i] = bih0[i] + bhh0[i];
    g_bias1[i] = bih1[i] + bhh1[i];
    if (i < 16) { g_cnt[i] = 0u; g_flag[i] = 0u; }
}

// ---------------- K1: pack/transpose recurrent weights to fp16 [k][row] ----------------
// grid (8 ktile, 8 rank, 32 = m*16+b), 256 threads; tile = 64 k x 256 rows
__global__ void k1_pack(const float* __restrict__ whh0, const float* __restrict__ wih1,
                        const float* __restrict__ whh1) {
    __shared__ __align__(16) __half sm[64 * 264];
    int kt = blockIdx.x, r = blockIdx.y;
    int mb = blockIdx.z; int m = mb >> 4, b = mb & 15;
    int tid = threadIdx.x;
    int grow = ((tid >> 6) << 9) + (r << 6) + (tid & 63);
    int k0 = kt * 64;
    const float* s0 = (m == 0 ? whh0 : wih1) + ((size_t)(b * 2048 + grow) * 512 + k0);
    const float* s1 = whh1 + ((size_t)(b * 2048 + grow) * 512 + k0);
#pragma unroll
    for (int q = 0; q < 16; q++) {
        float4 v = *(const float4*)(s0 + q * 4);
        if (m) {
            float4 u = *(const float4*)(s1 + q * 4);
            v.x += u.x; v.y += u.y; v.z += u.z; v.w += u.w;
        }
        sm[(q * 4 + 0) * 264 + tid] = __float2half(v.x);
        sm[(q * 4 + 1) * 264 + tid] = __float2half(v.y);
        sm[(q * 4 + 2) * 264 + tid] = __float2half(v.z);
        sm[(q * 4 + 3) * 264 + tid] = __float2half(v.w);
    }
    __syncthreads();
    __half* out = &g_warr[(((size_t)mb) * 8u + r) * 512u * 256u + (size_t)k0 * 256u];
    int kk = tid >> 2, rb = (tid & 3) * 64;
    const uint4* src = (const uint4*)(sm + kk * 264 + rb);
    uint4* dst = (uint4*)(out + kk * 256 + rb);
#pragma unroll
    for (int q = 0; q < 8; q++) dst[q] = src[q];
}

// ---------------- K2: precompute gi0[b][t][row] = wih0@x_t + bias0 ----------------
__global__ void k2_gemm(const float* __restrict__ wih0, const float* __restrict__ x) {
    __shared__ float As[64][17];
    __shared__ float Bs[16][65];
    int rt = blockIdx.x, tt = blockIdx.y, b = blockIdx.z;
    int row0 = rt * 64, t0 = tt * 64;
    int tid = threadIdx.x;
    int lm = tid >> 2, kq = tid & 3;
    const float* Ap = wih0 + ((size_t)(b * 2048 + row0 + lm) * 512 + kq * 4);
    const float* Bp = x + ((size_t)(b * 256 + t0 + lm) * 512 + kq * 4);
    int ty = tid >> 4, tx = tid & 15;
    float C[4][4];
#pragma unroll
    for (int i = 0; i < 4; i++)
#pragma unroll
        for (int j = 0; j < 4; j++) C[i][j] = 0.f;

    for (int kc = 0; kc < 512; kc += 16) {
        float4 a4 = *(const float4*)(Ap + kc);
        float4 b4 = *(const float4*)(Bp + kc);
        As[lm][kq * 4 + 0] = a4.x; As[lm][kq * 4 + 1] = a4.y;
        As[lm][kq * 4 + 2] = a4.z; As[lm][kq * 4 + 3] = a4.w;
        Bs[kq * 4 + 0][lm] = b4.x; Bs[kq * 4 + 1][lm] = b4.y;
        Bs[kq * 4 + 2][lm] = b4.z; Bs[kq * 4 + 3][lm] = b4.w;
        __syncthreads();
#pragma unroll
        for (int kk = 0; kk < 16; kk++) {
            float a[4], bb[4];
#pragma unroll
            for (int i = 0; i < 4; i++) a[i] = As[ty * 4 + i][kk];
#pragma unroll
            for (int j = 0; j < 4; j++) bb[j] = Bs[kk][tx * 4 + j];
#pragma unroll
            for (int i = 0; i < 4; i++)
#pragma unroll
                for (int j = 0; j < 4; j++) C[i][j] += a[i] * bb[j];
        }
        __syncthreads();
    }
    float4 bias = *(const float4*)&g_bias0[b * 2048 + row0 + ty * 4];
#pragma unroll
    for (int j = 0; j < 4; j++) {
        float4 vo;
        vo.x = C[0][j] + bias.x; vo.y = C[1][j] + bias.y;
        vo.z = C[2][j] + bias.z; vo.w = C[3][j] + bias.w;
        *(float4*)&g_gi0[((size_t)(b * 256 + t0 + tx * 4 + j)) * 2048 + row0 + ty * 4] = vo;
    }
}

// ---------------- K3: persistent recurrent kernel ----------------
// 128 CTAs x 256 threads. group g = batch, rank r owns h[64r..64r+64) + its 256 gate rows.
// 2 exchanges per layer-iter: (1) gate LN partial stats, (2) merged (c,o) publish, after
// which every rank redundantly computes global c-stats and the FULL h vector locally.
__global__ void __launch_bounds__(256, 1)
k3_lstm(const float* __restrict__ ln_w, const float* __restrict__ ln_b, float* __restrict__ y) {
    __shared__ float h_s[512];
    __shared__ float red[8][256];
    __shared__ float act_s[256];
    __shared__ float wpart[8][2];
    __shared__ float gwf[2 * 512], gbf[2 * 512];   // full LN params, both layers
    __shared__ float bias1_s[256];

    int bid = blockIdx.x;
    int g = bid >> 3, r = bid & 7;
    int tid = threadIdx.x, warp = tid >> 5, lane = tid & 31;
    int gate = tid >> 6, jl = tid & 63;

    h_s[tid] = 0.f; h_s[tid + 256] = 0.f;
    for (int i = tid; i < 1024; i += 256) { gwf[i] = ln_w[i]; gbf[i] = ln_b[i]; }
    bias1_s[tid] = g_bias1[g * 2048 + (gate << 9) + (r << 6) + jl];
    __syncthreads();

    float c_r = 0.f;           // cell state: thread tid<64 owns j = r*64 + tid
    unsigned bar = 0;

    for (int t = 0; t < 256; t++) {
        const float* gi0_t = &g_gi0[((size_t)(g * 256 + t)) * 2048];
        for (int l = 0; l < 2; l++) {
            // ---- per-row additive term (issue load early) ----
            int rowg = (gate << 9) + (r << 6) + jl;
            float gin = l ? bias1_s[tid] : __ldcg(gi0_t + rowg);

            // ---- matvec: 256 rows x K=512; warp w owns k-range [64w,64w+64) ----
            const __half* W = &g_warr[(((size_t)(l * 16 + g)) * 8u + r) * 512u * 256u];
            const uint4* Wp = (const uint4*)(W) + (size_t)warp * 2048 + lane;
            float acc[8];
#pragma unroll
            for (int i = 0; i < 8; i++) acc[i] = 0.f;
#pragma unroll 8
            for (int kk = 0; kk < 64; kk++) {
                uint4 w4 = __ldcg(Wp + (size_t)kk * 32);
                float hk = h_s[warp * 64 + kk];
                const __half2* hp = (const __half2*)&w4;
                float2 f0 = __half22float2(hp[0]);
                float2 f1 = __half22float2(hp[1]);
                float2 f2 = __half22float2(hp[2]);
                float2 f3 = __half22float2(hp[3]);
                acc[0] += hk * f0.x; acc[1] += hk * f0.y;
                acc[2] += hk * f1.x; acc[3] += hk * f1.y;
                acc[4] += hk * f2.x; acc[5] += hk * f2.y;
                acc[6] += hk * f3.x; acc[7] += hk * f3.y;
            }
            *(float4*)&red[warp][lane * 8]     = make_float4(acc[0], acc[1], acc[2], acc[3]);
            *(float4*)&red[warp][lane * 8 + 4] = make_float4(acc[4], acc[5], acc[6], acc[7]);
            __syncthreads();
            float v = gin;
#pragma unroll
            for (int w = 0; w < 8; w++) v += red[w][tid];

            // ---- gate LN partial stats (2 warps per gate) ----
            float s = v, q = v * v;
#pragma unroll
            for (int o = 16; o > 0; o >>= 1) {
                s += __shfl_xor_sync(0xffffffffu, s, o);
                q += __shfl_xor_sync(0xffffffffu, q, o);
            }
            if (lane == 0) { wpart[warp][0] = s; wpart[warp][1] = q; }
            __syncthreads();
            if (tid < 4) {
                float2 p;
                p.x = wpart[2 * tid][0] + wpart[2 * tid + 1][0];
                p.y = wpart[2 * tid][1] + wpart[2 * tid + 1][1];
                __stcg(&g_part[(g * 8 + r) * 4 + tid], p);
            }
            group_barrier(g, ++bar);          // X1: gate partials visible

            // ---- finalize gate LN + activation ----
            {
                float Ssum = 0.f, Q = 0.f;
#pragma unroll
                for (int rr = 0; rr < 8; rr++) {
                    float2 p = __ldcg(&g_part[(g * 8 + rr) * 4 + gate]);
                    Ssum += p.x; Q += p.y;
                }
                float mean = Ssum * (1.f / 512.f);
                float var  = Q * (1.f / 512.f) - mean * mean;
                float rstd = rsqrtf(var + EPS);
                float xn = (v - mean) * rstd * gwf[(l << 9) + (r << 6) + jl] + gbf[(l << 9) + (r << 6) + jl];
                act_s[tid] = (gate == 2) ? fast_tanh(xn) : fast_sigmoid(xn);
            }
            __syncthreads();

            // ---- c update + publish (c, o) for own j-slice ----
            if (tid < 64) {
                c_r = act_s[64 + tid] * c_r + act_s[tid] * act_s[128 + tid];
                __stcg(&g_co[g * 512 + r * 64 + tid], make_float2(c_r, act_s[192 + tid]));
            }
            group_barrier(g, ++bar);          // X2: (c,o) pairs visible

            // ---- merged: every rank computes global c-stats + full h locally ----
            float2 p0 = __ldcg(&g_co[g * 512 + tid]);         // j = tid
            float2 p1 = __ldcg(&g_co[g * 512 + 256 + tid]);   // j = tid + 256
            {
                float s2 = p0.x + p1.x, q2 = p0.x * p0.x + p1.x * p1.x;
#pragma unroll
                for (int o = 16; o > 0; o >>= 1) {
                    s2 += __shfl_xor_sync(0xffffffffu, s2, o);
                    q2 += __shfl_xor_sync(0xffffffffu, q2, o);
                }
                if (lane == 0) { wpart[warp][0] = s2; wpart[warp][1] = q2; }
            }
            __syncthreads();
            {
                float Sc = 0.f, Qc = 0.f;
#pragma unroll
                for (int w = 0; w < 8; w++) { Sc += wpart[w][0]; Qc += wpart[w][1]; }
                float mean = Sc * (1.f / 512.f);
                float var  = Qc * (1.f / 512.f) - mean * mean;
                float rstd = rsqrtf(var + EPS);
                int j0 = tid, j1 = tid + 256;
                float h0 = p0.y * fast_tanh((p0.x - mean) * rstd * gwf[(l << 9) + j0] + gbf[(l << 9) + j0]);
                float h1 = p1.y * fast_tanh((p1.x - mean) * rstd * gwf[(l << 9) + j1] + gbf[(l << 9) + j1]);
                h_s[j0] = h0;
                h_s[j1] = h1;
                if (l == 1) {
                    float* yt = &y[((size_t)(g * 256 + t)) * 512];
                    if ((j0 >> 6) == r) yt[j0] = h0;
                    if ((j1 >> 6) == r) yt[j1] = h1;
                }
            }
            __syncthreads();
        }
    }
}

// ---------------- launcher ----------------
extern "C" void kernel_launch(void* const* d_in, const int* in_sizes, int n_in,
                              void* d_out, int out_size) {
    (void)in_sizes; (void)n_in; (void)out_size;
    const float* x    = (const float*)d_in[0];
    const float* wih0 = (const float*)d_in[1];
    const float* whh0 = (const float*)d_in[2];
    const float* bih0 = (const float*)d_in[3];
    const float* bhh0 = (const float*)d_in[4];
    const float* wih1 = (const float*)d_in[5];
    const float* whh1 = (const float*)d_in[6];
    const float* bih1 = (const float*)d_in[7];
    const float* bhh1 = (const float*)d_in[8];
    const float* ln_w = (const float*)d_in[9];
    const float* ln_b = (const float*)d_in[10];
    float* y = (float*)d_out;

    k0_init<<<128, 256>>>(bih0, bhh0, bih1, bhh1);
    k1_pack<<<dim3(8, 8, 32), 256>>>(whh0, wih1, whh1);
    k2_gemm<<<dim3(32, 4, 16), 256>>>(wih0, x);
    k3_lstm<<<128, 256>>>(ln_w, ln_b, y);
}

// round 10
// speedup vs baseline: 1.9828x; 1.1193x over previous
#include <cuda_runtime.h>
#include <cuda_fp16.h>
#include <cstdint>

#define EPS 1e-5f
#define RD 6            // smem ring depth (chunks of 32KB)

// ---------------- device globals (scratch; no allocations allowed) ----------------
// packed recurrent weights: [m][b][r][k=512][rowlocal=256] fp16 ; m=0: whh0, m=1: wih1+whh1
__device__ __half g_warr[2u * 16u * 8u * 512u * 256u];                 // 67.1 MB
__device__ float g_gi0[16u * 256u * 2048u];                            // 33.5 MB: wih0@x + bias0
__device__ float g_bias0[16u * 2048u];
__device__ float g_bias1[16u * 2048u];
__device__ float2 g_part[16u * 8u * 4u];                               // gate stats: [b][rank][gate]
__device__ float2 g_co[16u * 512u];                                    // (c, o) pairs: [b][j]
__device__ unsigned g_cnt[16];
__device__ unsigned g_flag[16];

// ---------------- helpers ----------------
__device__ __forceinline__ uint32_t smem_u32(const void* p) {
    uint32_t a;
    asm("{ .reg .u64 t; cvta.to.shared.u64 t, %1; cvt.u32.u64 %0, t; }" : "=r"(a) : "l"(p));
    return a;
}
__device__ __forceinline__ void cpa16(uint32_t dst, const void* src) {
    asm volatile("cp.async.cg.shared.global [%0], [%1], 16;" :: "r"(dst), "l"(src) : "memory");
}
__device__ __forceinline__ float fast_rcp(float x) {
    float r; asm("rcp.approx.f32 %0, %1;" : "=f"(r) : "f"(x)); return r;
}
__device__ __forceinline__ float fast_sigmoid(float x) {
    return fast_rcp(1.0f + __expf(-x));
}
__device__ __forceinline__ float fast_tanh(float x) {
    return 2.0f * fast_rcp(1.0f + __expf(-2.0f * x)) - 1.0f;
}

// group barrier among the 8 CTAs of group g via scoped atomics (no full membar).
__device__ __forceinline__ void group_barrier(int g, unsigned target) {
    __syncthreads();
    if (threadIdx.x == 0) {
        unsigned v;
        asm volatile("atom.add.acq_rel.gpu.global.u32 %0, [%1], 1;"
                     : "=r"(v) : "l"(&g_cnt[g]) : "memory");
        if (v + 1u == target * 8u) {
            asm volatile("st.release.gpu.global.u32 [%0], %1;"
                         :: "l"(&g_flag[g]), "r"(target) : "memory");
        } else {
            unsigned f;
            do {
                asm volatile("ld.acquire.gpu.global.u32 %0, [%1];"
                             : "=r"(f) : "l"(&g_flag[g]) : "memory");
            } while (f < target);
        }
    }
    __syncthreads();
}

// ---------------- K0: per-launch init ----------------
__global__ void k0_init(const float* __restrict__ bih0, const float* __restrict__ bhh0,
                        const float* __restrict__ bih1, const float* __restrict__ bhh1) {
    int i = blockIdx.x * blockDim.x + threadIdx.x;   // 32768 = 16*2048
    g_bias0[i] = bih0[i] + bhh0[i];
    g_bias1[i] = bih1[i] + bhh1[i];
    if (i < 16) { g_cnt[i] = 0u; g_flag[i] = 0u; }
}

// ---------------- K1: pack/transpose recurrent weights to fp16 [k][row] ----------------
// grid (8 ktile, 8 rank, 32 = m*16+b), 256 threads; tile = 64 k x 256 rows
__global__ void k1_pack(const float* __restrict__ whh0, const float* __restrict__ wih1,
                        const float* __restrict__ whh1) {
    __shared__ __align__(16) __half sm[64 * 264];
    int kt = blockIdx.x, r = blockIdx.y;
    int mb = blockIdx.z; int m = mb >> 4, b = mb & 15;
    int tid = threadIdx.x;
    int grow = ((tid >> 6) << 9) + (r << 6) + (tid & 63);
    int k0 = kt * 64;
    const float* s0 = (m == 0 ? whh0 : wih1) + ((size_t)(b * 2048 + grow) * 512 + k0);
    const float* s1 = whh1 + ((size_t)(b * 2048 + grow) * 512 + k0);
#pragma unroll
    for (int q = 0; q < 16; q++) {
        float4 v = *(const float4*)(s0 + q * 4);
        if (m) {
            float4 u = *(const float4*)(s1 + q * 4);
            v.x += u.x; v.y += u.y; v.z += u.z; v.w += u.w;
        }
        sm[(q * 4 + 0) * 264 + tid] = __float2half(v.x);
        sm[(q * 4 + 1) * 264 + tid] = __float2half(v.y);
        sm[(q * 4 + 2) * 264 + tid] = __float2half(v.z);
        sm[(q * 4 + 3) * 264 + tid] = __float2half(v.w);
    }
    __syncthreads();
    __half* out = &g_warr[(((size_t)mb) * 8u + r) * 512u * 256u + (size_t)k0 * 256u];
    int kk = tid >> 2, rb = (tid & 3) * 64;
    const uint4* src = (const uint4*)(sm + kk * 264 + rb);
    uint4* dst = (uint4*)(out + kk * 256 + rb);
#pragma unroll
    for (int q = 0; q < 8; q++) dst[q] = src[q];
}

// ---------------- K2: precompute gi0[b][t][row] = wih0@x_t + bias0 ----------------
__global__ void k2_gemm(const float* __restrict__ wih0, const float* __restrict__ x) {
    __shared__ float As[64][17];
    __shared__ float Bs[16][65];
    int rt = blockIdx.x, tt = blockIdx.y, b = blockIdx.z;
    int row0 = rt * 64, t0 = tt * 64;
    int tid = threadIdx.x;
    int lm = tid >> 2, kq = tid & 3;
    const float* Ap = wih0 + ((size_t)(b * 2048 + row0 + lm) * 512 + kq * 4);
    const float* Bp = x + ((size_t)(b * 256 + t0 + lm) * 512 + kq * 4);
    int ty = tid >> 4, tx = tid & 15;
    float C[4][4];
#pragma unroll
    for (int i = 0; i < 4; i++)
#pragma unroll
        for (int j = 0; j < 4; j++) C[i][j] = 0.f;

    for (int kc = 0; kc < 512; kc += 16) {
        float4 a4 = *(const float4*)(Ap + kc);
        float4 b4 = *(const float4*)(Bp + kc);
        As[lm][kq * 4 + 0] = a4.x; As[lm][kq * 4 + 1] = a4.y;
        As[lm][kq * 4 + 2] = a4.z; As[lm][kq * 4 + 3] = a4.w;
        Bs[kq * 4 + 0][lm] = b4.x; Bs[kq * 4 + 1][lm] = b4.y;
        Bs[kq * 4 + 2][lm] = b4.z; Bs[kq * 4 + 3][lm] = b4.w;
        __syncthreads();
#pragma unroll
        for (int kk = 0; kk < 16; kk++) {
            float a[4], bb[4];
#pragma unroll
            for (int i = 0; i < 4; i++) a[i] = As[ty * 4 + i][kk];
#pragma unroll
            for (int j = 0; j < 4; j++) bb[j] = Bs[kk][tx * 4 + j];
#pragma unroll
            for (int i = 0; i < 4; i++)
#pragma unroll
                for (int j = 0; j < 4; j++) C[i][j] += a[i] * bb[j];
        }
        __syncthreads();
    }
    float4 bias = *(const float4*)&g_bias0[b * 2048 + row0 + ty * 4];
#pragma unroll
    for (int j = 0; j < 4; j++) {
        float4 vo;
        vo.x = C[0][j] + bias.x; vo.y = C[1][j] + bias.y;
        vo.z = C[2][j] + bias.z; vo.w = C[3][j] + bias.w;
        *(float4*)&g_gi0[((size_t)(b * 256 + t0 + tx * 4 + j)) * 2048 + row0 + ty * 4] = vo;
    }
}

// ---------------- K3: persistent recurrent kernel ----------------
// 128 CTAs x 256 threads. group g = batch, rank r owns h[64r..64r+64) + its 256 gate rows.
// Weight stream decoupled via cp.async 6-slot smem ring: warp w copies & consumes only its
// own k-rows [8w,8w+8) of each 64-k chunk (lane-private 16B pieces -> per-thread wait only).
// Issue runs 5 chunks ahead of compute, overlapping L2 ingest with the sync/LN phases.
struct K3S {
    __half wring[RD * 64 * 256];   // 196608 B: RD chunk slots, [k64][row256]
    float h_s[512];
    float red[8][256];
    float act_s[256];
    float wpart[8][2];
    float gwf[1024], gbf[1024];    // LN params, both layers
    float bias1_s[256];
};

__global__ void __launch_bounds__(256, 1)
k3_lstm(const float* __restrict__ ln_w, const float* __restrict__ ln_b, float* __restrict__ y) {
    extern __shared__ __align__(16) unsigned char sraw[];
    K3S* S = (K3S*)sraw;

    int bid = blockIdx.x;
    int g = bid >> 3, r = bid & 7;
    int tid = threadIdx.x, warp = tid >> 5, lane = tid & 31;
    int gate = tid >> 6, jl = tid & 63;

    const uint4* Wl[2];
    Wl[0] = (const uint4*)&g_warr[(((size_t)(0 * 16 + g)) * 8u + r) * 512u * 256u];
    Wl[1] = (const uint4*)&g_warr[(((size_t)(1 * 16 + g)) * 8u + r) * 512u * 256u];
    uint32_t wring_a = smem_u32(S->wring) + (uint32_t)(warp * 256 + lane) * 16u;

    // issue-side state (5 chunks ahead of compute)
    int iss_it = 0, iss_c = 0, iss_slot = 0;
#define ISSUE_CHUNK() do {                                                          \
        if (iss_it < 512) {                                                         \
            const uint4* _src = Wl[iss_it & 1] + (size_t)((iss_c * 64 + warp * 8) * 32 + lane); \
            uint32_t _dst = wring_a + (uint32_t)(iss_slot * 32768);                 \
            _Pragma("unroll")                                                       \
            for (int _i = 0; _i < 8; _i++) cpa16(_dst + _i * 512u, _src + _i * 32); \
        }                                                                           \
        asm volatile("cp.async.commit_group;" ::: "memory");                        \
        if (++iss_c == 8) { iss_c = 0; iss_it++; }                                  \
        if (++iss_slot == RD) iss_slot = 0;                                         \
    } while (0)

    // prologue: start the pipeline (chunks 0..4), init state
    ISSUE_CHUNK(); ISSUE_CHUNK(); ISSUE_CHUNK(); ISSUE_CHUNK(); ISSUE_CHUNK();
    S->h_s[tid] = 0.f; S->h_s[tid + 256] = 0.f;
    for (int i = tid; i < 1024; i += 256) { S->gwf[i] = ln_w[i]; S->gbf[i] = ln_b[i]; }
    S->bias1_s[tid] = g_bias1[g * 2048 + (gate << 9) + (r << 6) + jl];
    __syncthreads();

    float c_r = 0.f;           // cell state: thread tid<64 owns j = r*64 + tid
    unsigned bar = 0;
    int comp_slot = 0;

    for (int t = 0; t < 256; t++) {
        const float* gi0_t = &g_gi0[((size_t)(g * 256 + t)) * 2048];
        for (int l = 0; l < 2; l++) {
            // ---- per-row additive term (issue load early) ----
            int rowg = (gate << 9) + (r << 6) + jl;
            float gin = l ? S->bias1_s[tid] : __ldcg(gi0_t + rowg);

            // ---- matvec via smem ring: 8 chunks; warp w uses k = 64c + 8w + i ----
            float acc[8];
#pragma unroll
            for (int i = 0; i < 8; i++) acc[i] = 0.f;
#pragma unroll 1
            for (int c = 0; c < 8; c++) {
                ISSUE_CHUNK();
                asm volatile("cp.async.wait_group 5;" ::: "memory");
                const uint4* wp = (const uint4*)S->wring + comp_slot * 2048 + warp * 256 + lane;
                const float* hp_s = &S->h_s[c * 64 + warp * 8];
#pragma unroll
                for (int i = 0; i < 8; i++) {
                    uint4 w4 = wp[i * 32];
                    float hk = hp_s[i];
                    const __half2* hp = (const __half2*)&w4;
                    float2 f0 = __half22float2(hp[0]);
                    float2 f1 = __half22float2(hp[1]);
                    float2 f2 = __half22float2(hp[2]);
                    float2 f3 = __half22float2(hp[3]);
                    acc[0] += hk * f0.x; acc[1] += hk * f0.y;
                    acc[2] += hk * f1.x; acc[3] += hk * f1.y;
                    acc[4] += hk * f2.x; acc[5] += hk * f2.y;
                    acc[6] += hk * f3.x; acc[7] += hk * f3.y;
                }
                if (++comp_slot == RD) comp_slot = 0;
            }
            *(float4*)&S->red[warp][lane * 8]     = make_float4(acc[0], acc[1], acc[2], acc[3]);
            *(float4*)&S->red[warp][lane * 8 + 4] = make_float4(acc[4], acc[5], acc[6], acc[7]);
            __syncthreads();
            float v = gin;
#pragma unroll
            for (int w = 0; w < 8; w++) v += S->red[w][tid];

            // ---- gate LN partial stats (2 warps per gate) ----
            float s = v, q = v * v;
#pragma unroll
            for (int o = 16; o > 0; o >>= 1) {
                s += __shfl_xor_sync(0xffffffffu, s, o);
                q += __shfl_xor_sync(0xffffffffu, q, o);
            }
            if (lane == 0) { S->wpart[warp][0] = s; S->wpart[warp][1] = q; }
            __syncthreads();
            if (tid < 4) {
                float2 p;
                p.x = S->wpart[2 * tid][0] + S->wpart[2 * tid + 1][0];
                p.y = S->wpart[2 * tid][1] + S->wpart[2 * tid + 1][1];
                __stcg(&g_part[(g * 8 + r) * 4 + tid], p);
            }
            group_barrier(g, ++bar);          // X1: gate partials visible

            // ---- finalize gate LN + activation ----
            {
                float Ssum = 0.f, Q = 0.f;
#pragma unroll
                for (int rr = 0; rr < 8; rr++) {
                    float2 p = __ldcg(&g_part[(g * 8 + rr) * 4 + gate]);
                    Ssum += p.x; Q += p.y;
                }
                float mean = Ssum * (1.f / 512.f);
                float var  = Q * (1.f / 512.f) - mean * mean;
                float rstd = rsqrtf(var + EPS);
                float xn = (v - mean) * rstd * S->gwf[(l << 9) + (r << 6) + jl]
                         + S->gbf[(l << 9) + (r << 6) + jl];
                S->act_s[tid] = (gate == 2) ? fast_tanh(xn) : fast_sigmoid(xn);
            }
            __syncthreads();

            // ---- c update + publish (c, o) for own j-slice ----
            if (tid < 64) {
                c_r = S->act_s[64 + tid] * c_r + S->act_s[tid] * S->act_s[128 + tid];
                __stcg(&g_co[g * 512 + r * 64 + tid], make_float2(c_r, S->act_s[192 + tid]));
            }
            group_barrier(g, ++bar);          // X2: (c,o) pairs visible

            // ---- merged: every rank computes global c-stats + full h locally ----
            float2 p0 = __ldcg(&g_co[g * 512 + tid]);         // j = tid
            float2 p1 = __ldcg(&g_co[g * 512 + 256 + tid]);   // j = tid + 256
            {
                float s2 = p0.x + p1.x, q2 = p0.x * p0.x + p1.x * p1.x;
#pragma unroll
                for (int o = 16; o > 0; o >>= 1) {
                    s2 += __shfl_xor_sync(0xffffffffu, s2, o);
                    q2 += __shfl_xor_sync(0xffffffffu, q2, o);
                }
                if (lane == 0) { S->wpart[warp][0] = s2; S->wpart[warp][1] = q2; }
            }
            __syncthreads();
            {
                float Sc = 0.f, Qc = 0.f;
#pragma unroll
                for (int w = 0; w < 8; w++) { Sc += S->wpart[w][0]; Qc += S->wpart[w][1]; }
                float mean = Sc * (1.f / 512.f);
                float var  = Qc * (1.f / 512.f) - mean * mean;
                float rstd = rsqrtf(var + EPS);
                int j0 = tid, j1 = tid + 256;
                float h0 = p0.y * fast_tanh((p0.x - mean) * rstd * S->gwf[(l << 9) + j0] + S->gbf[(l << 9) + j0]);
                float h1 = p1.y * fast_tanh((p1.x - mean) * rstd * S->gwf[(l << 9) + j1] + S->gbf[(l << 9) + j1]);
                S->h_s[j0] = h0;
                S->h_s[j1] = h1;
                if (l == 1) {
                    float* yt = &y[((size_t)(g * 256 + t)) * 512];
                    if ((j0 >> 6) == r) yt[j0] = h0;
                    if ((j1 >> 6) == r) yt[j1] = h1;
                }
            }
            __syncthreads();
        }
    }
#undef ISSUE_CHUNK
}

// ---------------- launcher ----------------
extern "C" void kernel_launch(void* const* d_in, const int* in_sizes, int n_in,
                              void* d_out, int out_size) {
    (void)in_sizes; (void)n_in; (void)out_size;
    const float* x    = (const float*)d_in[0];
    const float* wih0 = (const float*)d_in[1];
    const float* whh0 = (const float*)d_in[2];
    const float* bih0 = (const float*)d_in[3];
    const float* bhh0 = (const float*)d_in[4];
    const float* wih1 = (const float*)d_in[5];
    const float* whh1 = (const float*)d_in[6];
    const float* bih1 = (const float*)d_in[7];
    const float* bhh1 = (const float*)d_in[8];
    const float* ln_w = (const float*)d_in[9];
    const float* ln_b = (const float*)d_in[10];
    float* y = (float*)d_out;

    cudaFuncSetAttribute(k3_lstm, cudaFuncAttributeMaxDynamicSharedMemorySize,
                         (int)sizeof(K3S));

    k0_init<<<128, 256>>>(bih0, bhh0, bih1, bhh1);
    k1_pack<<<dim3(8, 8, 32), 256>>>(whh0, wih1, whh1);
    k2_gemm<<<dim3(32, 4, 16), 256>>>(wih0, x);
    k3_lstm<<<128, 256, sizeof(K3S)>>>(ln_w, ln_b, y);
}